// round 1
// baseline (speedup 1.0000x reference)
#include <cuda_runtime.h>
#include <math.h>

#define NN   65536
#define KX   512
#define AA   64
#define CWIN 16
#define DD   8
#define PP   96
#define NB2  (NN/128)   // 512 blocks in K2
#define MOMW (AA + AA*AA) // 4160

// ---------------- scratch (device globals; no allocation) ----------------
__device__ __align__(16) float g_t  [(size_t)NN*AA];      // normalized t
__device__ __align__(16) float g_rep[(size_t)NN*AA];      // rep
__device__ __align__(16) float g_part[(size_t)NB2*MOMW];  // per-block moment partials
__device__ __align__(16) float g_m[AA];
__device__ __align__(16) float g_S[AA*AA];
__device__ __align__(16) float g_T[DD*AA*AA];
__device__ __align__(16) float g_scale[DD*AA];
__device__ __align__(16) float g_shift[DD*AA];
__device__ __align__(16) float g_E[(size_t)NN*DD*AA];     // post-ELU activations (128MB)

__device__ __forceinline__ float eluf(float v) { return v > 0.f ? v : expm1f(v); }

// ---------------- K1: t = normalize_rows(x @ shuzhihua) ----------------
// grid NN/64, 256 thr; block tile 64 rows x 64 cols; thread 4x4
__global__ __launch_bounds__(256) void k1_gemm_norm(const float* __restrict__ x,
                                                    const float* __restrict__ B) {
    __shared__ float As[64][65];
    __shared__ __align__(16) float Bs[64][68];
    __shared__ float red[64][17];
    __shared__ float rs[64];
    int row0 = blockIdx.x * 64;
    int tid = threadIdx.x;
    int tc = tid & 15, tr = tid >> 4;
    int r0 = tr * 4, c0 = tc * 4;
    float acc[4][4] = {};
    for (int k0 = 0; k0 < KX; k0 += 64) {
        for (int l = tid; l < 64 * 64; l += 256) {
            int r = l >> 6, kk = l & 63;
            As[r][kk] = x[(size_t)(row0 + r) * KX + k0 + kk];
        }
        for (int l = tid; l < 64 * 64; l += 256) {
            int kk = l >> 6, c = l & 63;
            Bs[kk][c] = B[(size_t)(k0 + kk) * AA + c];
        }
        __syncthreads();
#pragma unroll 16
        for (int kk = 0; kk < 64; ++kk) {
            float4 bv = *(const float4*)&Bs[kk][c0];
            float av[4];
#pragma unroll
            for (int i = 0; i < 4; i++) av[i] = As[r0 + i][kk];
#pragma unroll
            for (int i = 0; i < 4; i++) {
                acc[i][0] = fmaf(av[i], bv.x, acc[i][0]);
                acc[i][1] = fmaf(av[i], bv.y, acc[i][1]);
                acc[i][2] = fmaf(av[i], bv.z, acc[i][2]);
                acc[i][3] = fmaf(av[i], bv.w, acc[i][3]);
            }
        }
        __syncthreads();
    }
#pragma unroll
    for (int i = 0; i < 4; i++) {
        float ss = acc[i][0]*acc[i][0] + acc[i][1]*acc[i][1]
                 + acc[i][2]*acc[i][2] + acc[i][3]*acc[i][3];
        red[r0 + i][tc] = ss;
    }
    __syncthreads();
    if (tid < 64) {
        float s = 0.f;
#pragma unroll
        for (int q = 0; q < 16; q++) s += red[tid][q];
        rs[tid] = 1.0f / fmaxf(sqrtf(s), 1e-12f);
    }
    __syncthreads();
#pragma unroll
    for (int i = 0; i < 4; i++) {
        float sc = rs[r0 + i];
        float4 v = make_float4(acc[i][0]*sc, acc[i][1]*sc, acc[i][2]*sc, acc[i][3]*sc);
        *(float4*)&g_t[(size_t)(row0 + r0 + i) * AA + c0] = v;
    }
}

// ---------------- K2: rep window-sum + per-block moments ----------------
// grid NN/128, 256 thr
__global__ __launch_bounds__(256) void k2_rep(const float* __restrict__ lw,
                                              const float* __restrict__ lb,
                                              float* __restrict__ orep) {
    __shared__ float ts[143 * 64];
    __shared__ float ws[16 * 64];
    __shared__ float bsum[64];
    __shared__ float mred[4][64];
    int row0 = blockIdx.x * 128;
    int base = row0 - 15;
    int tid = threadIdx.x;
    for (int l = tid; l < 143 * 64; l += 256) {
        int r = l >> 6, a = l & 63;
        int g = base + r; if (g < 0) g = 0;
        ts[l] = g_t[(size_t)g * 64 + a];
    }
    for (int l = tid; l < 1024; l += 256) ws[l] = lw[l];
    if (tid < 64) {
        float s = 0.f;
        for (int j = 0; j < 16; j++) s += lb[j * 64 + tid];
        bsum[tid] = s;
    }
    __syncthreads();
    int a = tid & 63, rg = tid >> 6;
    float ms = 0.f;
    for (int i = 0; i < 32; i++) {
        int r = rg * 32 + i;
        int n = row0 + r;
        float acc = bsum[a];
        if (n >= 15) {
#pragma unroll
            for (int j = 0; j < 16; j++) acc += ws[j * 64 + a] * ts[(r + j) * 64 + a];
        } else {
            for (int j = 0; j < 16; j++) {
                int lj = min(j, n) + 15;
                acc += ws[j * 64 + a] * ts[lj * 64 + a];
            }
        }
        g_rep[(size_t)n * 64 + a] = acc;
        if (orep) orep[(size_t)n * 64 + a] = acc;
        ms += acc;
    }
    mred[rg][a] = ms;
    __syncthreads();   // also makes this block's g_rep writes visible
    if (tid < 64)
        g_part[(size_t)blockIdx.x * MOMW + tid] =
            mred[0][tid] + mred[1][tid] + mred[2][tid] + mred[3][tid];
    // S partial: thread 4x4 tile of the 64x64 second-moment matrix
    int bi = tid & 15, ai = tid >> 4;
    int a4 = ai * 4, b4 = bi * 4;
    float sa[4][4] = {};
    const float* rp = &g_rep[(size_t)row0 * 64];
    for (int r = 0; r < 128; r++) {
        float4 av = *(const float4*)&rp[r * 64 + a4];
        float4 bv = *(const float4*)&rp[r * 64 + b4];
        float am[4] = {av.x, av.y, av.z, av.w};
        float bm[4] = {bv.x, bv.y, bv.z, bv.w};
#pragma unroll
        for (int i = 0; i < 4; i++)
#pragma unroll
            for (int j = 0; j < 4; j++) sa[i][j] = fmaf(am[i], bm[j], sa[i][j]);
    }
    float* sp = &g_part[(size_t)blockIdx.x * MOMW + 64];
#pragma unroll
    for (int i = 0; i < 4; i++)
        *(float4*)&sp[(a4 + i) * 64 + b4] = make_float4(sa[i][0], sa[i][1], sa[i][2], sa[i][3]);
}

// ---------------- K2b: reduce partials (deterministic) ----------------
__global__ void k2b_reduce() {
    int e = blockIdx.x * 128 + threadIdx.x;
    if (e >= MOMW) return;
    float s = 0.f;
    for (int k = 0; k < NB2; k++) s += g_part[(size_t)k * MOMW + e];
    if (e < 64) g_m[e] = s; else g_S[e - 64] = s;
}

// ---------------- K3a: T[d,i,b] = sum_j S[i,j] * W1[d,j,b] ----------------
__global__ __launch_bounds__(256) void k3a(const float* __restrict__ W1) {
    __shared__ float Ss[4096];
    int d = blockIdx.x, tid = threadIdx.x;
    for (int l = tid; l < 4096; l += 256) Ss[l] = g_S[l];
    __syncthreads();
    int b = tid & 63, iq = tid >> 6;
    const float* w = &W1[(size_t)d * 4096];
    for (int i = iq * 16; i < iq * 16 + 16; i++) {
        float acc = 0.f;
#pragma unroll 8
        for (int j = 0; j < 64; j++) acc = fmaf(Ss[i * 64 + j], w[j * 64 + b], acc);
        g_T[(size_t)d * 4096 + i * 64 + b] = acc;
    }
}

// ---------------- K3b: BN scale/shift per (d,b) ----------------
__global__ void k3b(const float* __restrict__ W1, const float* __restrict__ gamma,
                    const float* __restrict__ beta) {
    int d = blockIdx.x, b = threadIdx.x;
    const float invN = 1.0f / (float)NN;
    float mu = 0.f, q = 0.f;
    for (int i = 0; i < 64; i++) {
        float w = W1[(size_t)d * 4096 + i * 64 + b];
        mu = fmaf(g_m[i], w, mu);
        q  = fmaf(w, g_T[(size_t)d * 4096 + i * 64 + b], q);
    }
    float mean = mu * invN;
    float var = q * invN - mean * mean;
    float s = gamma[d * 64 + b] * rsqrtf(var + 1e-5f);
    g_scale[d * 64 + b] = s;
    g_shift[d * 64 + b] = beta[d * 64 + b] - mean * s;
}

// ---------------- K4a: E = ELU(scale*(rep@W1[d]) + shift) ----------------
// grid (NN/64, 8), 256 thr
__global__ __launch_bounds__(256) void k4a(const float* __restrict__ W1) {
    __shared__ float As[64][65];
    __shared__ __align__(16) float Bs[64][68];
    __shared__ float scl[64], shf[64];
    int row0 = blockIdx.x * 64;
    int d = blockIdx.y;
    int tid = threadIdx.x;
    for (int l = tid; l < 4096; l += 256) {
        int r = l >> 6, k = l & 63;
        As[r][k] = g_rep[(size_t)(row0 + r) * 64 + k];
    }
    for (int l = tid; l < 4096; l += 256) {
        int k = l >> 6, c = l & 63;
        Bs[k][c] = W1[(size_t)d * 4096 + l];
    }
    if (tid < 64) { scl[tid] = g_scale[d * 64 + tid]; shf[tid] = g_shift[d * 64 + tid]; }
    __syncthreads();
    int tc = tid & 15, tr = tid >> 4;
    int r0 = tr * 4, c0 = tc * 4;
    float acc[4][4] = {};
#pragma unroll 16
    for (int kk = 0; kk < 64; ++kk) {
        float4 bv = *(const float4*)&Bs[kk][c0];
        float av[4];
#pragma unroll
        for (int i = 0; i < 4; i++) av[i] = As[r0 + i][kk];
#pragma unroll
        for (int i = 0; i < 4; i++) {
            acc[i][0] = fmaf(av[i], bv.x, acc[i][0]);
            acc[i][1] = fmaf(av[i], bv.y, acc[i][1]);
            acc[i][2] = fmaf(av[i], bv.z, acc[i][2]);
            acc[i][3] = fmaf(av[i], bv.w, acc[i][3]);
        }
    }
    float s0 = scl[c0], s1 = scl[c0+1], s2 = scl[c0+2], s3 = scl[c0+3];
    float f0 = shf[c0], f1 = shf[c0+1], f2 = shf[c0+2], f3 = shf[c0+3];
#pragma unroll
    for (int i = 0; i < 4; i++) {
        float4 v;
        v.x = eluf(fmaf(acc[i][0], s0, f0));
        v.y = eluf(fmaf(acc[i][1], s1, f1));
        v.z = eluf(fmaf(acc[i][2], s2, f2));
        v.w = eluf(fmaf(acc[i][3], s3, f3));
        *(float4*)&g_E[(size_t)(row0 + r0 + i) * 512 + d * 64 + c0] = v;
    }
}

// ---------------- K4b: y[d] = E[d] @ W2[d] + b2[d], interleaved store ----------------
// grid (8, NN/64) -- d fastest so the 8 writers of each output sector are adjacent in time
__global__ __launch_bounds__(384) void k4b(const float* __restrict__ W2,
                                           const float* __restrict__ b2,
                                           float* __restrict__ out) {
    __shared__ float As[64][65];
    __shared__ __align__(16) float Bs[64][100];
    __shared__ float b2s[96];
    int d = blockIdx.x;
    int row0 = blockIdx.y * 64;
    int tid = threadIdx.x;
    for (int l = tid; l < 4096; l += 384) {
        int r = l >> 6, k = l & 63;
        As[r][k] = g_E[(size_t)(row0 + r) * 512 + d * 64 + k];
    }
    for (int l = tid; l < 6144; l += 384) {
        int k = l / 96, p = l - k * 96;
        Bs[k][p] = W2[(size_t)d * 6144 + l];
    }
    if (tid < 96) b2s[tid] = b2[d * 96 + tid];
    __syncthreads();
    int cg = tid % 24, rg = tid / 24;     // 24 col-groups x 16 row-groups
    int r0 = rg * 4, c0 = cg * 4;
    float acc[4][4] = {};
#pragma unroll 16
    for (int kk = 0; kk < 64; ++kk) {
        float4 bv = *(const float4*)&Bs[kk][c0];
        float av[4];
#pragma unroll
        for (int i = 0; i < 4; i++) av[i] = As[r0 + i][kk];
#pragma unroll
        for (int i = 0; i < 4; i++) {
            acc[i][0] = fmaf(av[i], bv.x, acc[i][0]);
            acc[i][1] = fmaf(av[i], bv.y, acc[i][1]);
            acc[i][2] = fmaf(av[i], bv.z, acc[i][2]);
            acc[i][3] = fmaf(av[i], bv.w, acc[i][3]);
        }
    }
#pragma unroll
    for (int i = 0; i < 4; i++)
#pragma unroll
        for (int j = 0; j < 4; j++)
            out[(size_t)(row0 + r0 + i) * 768 + (size_t)(c0 + j) * 8 + d] =
                acc[i][j] + b2s[c0 + j];
}

// ---------------- launch ----------------
extern "C" void kernel_launch(void* const* d_in, const int* in_sizes, int n_in,
                              void* d_out, int out_size) {
    const float* x     = (const float*)d_in[0];
    const float* shz   = (const float*)d_in[1];
    const float* lw    = (const float*)d_in[2];
    const float* lb    = (const float*)d_in[3];
    const float* W1    = (const float*)d_in[4];
    // d_in[5] = b1: cancels exactly inside BatchNorm (h - mu), unused
    const float* gamma = (const float*)d_in[6];
    const float* beta  = (const float*)d_in[7];
    const float* W2    = (const float*)d_in[8];
    const float* b2    = (const float*)d_in[9];
    float* out = (float*)d_out;

    float* orep = nullptr;
    if ((long long)out_size >= (long long)NN * 832)
        orep = out + (size_t)NN * 768;   // second output (rep) after y_1

    k1_gemm_norm<<<NN / 64, 256>>>(x, shz);
    k2_rep<<<NN / 128, 256>>>(lw, lb, orep);
    k2b_reduce<<<(MOMW + 127) / 128, 128>>>();
    k3a<<<DD, 256>>>(W1);
    k3b<<<DD, 64>>>(W1, gamma, beta);
    k4a<<<dim3(NN / 64, DD), 256>>>(W1);
    k4b<<<dim3(DD, NN / 64), 384>>>(W2, b2, out);
}

// round 2
// speedup vs baseline: 1.0882x; 1.0882x over previous
#include <cuda_runtime.h>
#include <math.h>

#define NN   65536
#define KX   512
#define AA   64
#define DD   8
#define PP   96
#define NB2  (NN/128)     // 512 moment-partial blocks
#define MOMW (AA + AA*AA) // 4160

// ---------------- scratch (device globals; no allocation) ----------------
__device__ __align__(16) float g_t  [(size_t)NN*AA];
__device__ __align__(16) float g_rep[(size_t)NN*AA];
__device__ __align__(16) float g_part[(size_t)NB2*MOMW];
__device__ __align__(16) float g_m[AA];
__device__ __align__(16) float g_S[AA*AA];
__device__ __align__(16) float g_scale[DD*AA];
__device__ __align__(16) float g_shift[DD*AA];

__device__ __forceinline__ float eluf(float v) { return v > 0.f ? v : expm1f(v); }

// ---------------- K1: t = normalize_rows(x @ shuzhihua) ----------------
// 128x64 block tile, 256 thr, 8x4 per thread. smem exactly 48KB; reduction
// buffers alias Bs after the mainloop.
__global__ __launch_bounds__(256) void k1_gemm_norm(const float* __restrict__ x,
                                                    const float* __restrict__ B) {
    __shared__ __align__(16) float As[128 * 64];
    __shared__ __align__(16) float Bs[64 * 64];
    int row0 = blockIdx.x * 128;
    int tid = threadIdx.x;
    int tc = tid & 15, tr = tid >> 4;
    int r0 = tr * 8, c0 = tc * 4;
    float acc[8][4] = {};
    for (int k0 = 0; k0 < KX; k0 += 64) {
        for (int l = tid; l < 2048; l += 256) {
            int kk4 = (l & 15) * 4, r = l >> 4;
            *(float4*)&As[r * 64 + kk4] =
                *(const float4*)&x[(size_t)(row0 + r) * KX + k0 + kk4];
        }
        for (int l = tid; l < 1024; l += 256) {
            int c4 = (l & 15) * 4, kk = l >> 4;
            *(float4*)&Bs[kk * 64 + c4] =
                *(const float4*)&B[(size_t)(k0 + kk) * AA + c4];
        }
        __syncthreads();
#pragma unroll 8
        for (int kk = 0; kk < 64; ++kk) {
            float4 bv = *(const float4*)&Bs[kk * 64 + c0];
            float av[8];
#pragma unroll
            for (int i = 0; i < 8; i++) av[i] = As[(r0 + i) * 64 + kk];
#pragma unroll
            for (int i = 0; i < 8; i++) {
                acc[i][0] = fmaf(av[i], bv.x, acc[i][0]);
                acc[i][1] = fmaf(av[i], bv.y, acc[i][1]);
                acc[i][2] = fmaf(av[i], bv.z, acc[i][2]);
                acc[i][3] = fmaf(av[i], bv.w, acc[i][3]);
            }
        }
        __syncthreads();
    }
    float* red = Bs;                 // 128*17 = 2176 floats
    float* rs  = Bs + 128 * 17;      // +128
#pragma unroll
    for (int i = 0; i < 8; i++) {
        float ss = acc[i][0]*acc[i][0] + acc[i][1]*acc[i][1]
                 + acc[i][2]*acc[i][2] + acc[i][3]*acc[i][3];
        red[(r0 + i) * 17 + tc] = ss;
    }
    __syncthreads();
    if (tid < 128) {
        float s = 0.f;
#pragma unroll
        for (int q = 0; q < 16; q++) s += red[tid * 17 + q];
        rs[tid] = 1.0f / fmaxf(sqrtf(s), 1e-12f);
    }
    __syncthreads();
#pragma unroll
    for (int i = 0; i < 8; i++) {
        float sc = rs[r0 + i];
        float4 v = make_float4(acc[i][0]*sc, acc[i][1]*sc, acc[i][2]*sc, acc[i][3]*sc);
        *(float4*)&g_t[(size_t)(row0 + r0 + i) * AA + c0] = v;
    }
}

// ---------------- K2: rep window-sum + per-block moments ----------------
__global__ __launch_bounds__(256) void k2_rep(const float* __restrict__ lw,
                                              const float* __restrict__ lb,
                                              float* __restrict__ orep) {
    __shared__ float ts[143 * 64];
    __shared__ float ws[16 * 64];
    __shared__ float bsum[64];
    __shared__ float mred[4][64];
    int row0 = blockIdx.x * 128;
    int base = row0 - 15;
    int tid = threadIdx.x;
    for (int l = tid; l < 143 * 64; l += 256) {
        int r = l >> 6, a = l & 63;
        int g = base + r; if (g < 0) g = 0;
        ts[l] = g_t[(size_t)g * 64 + a];
    }
    for (int l = tid; l < 1024; l += 256) ws[l] = lw[l];
    if (tid < 64) {
        float s = 0.f;
        for (int j = 0; j < 16; j++) s += lb[j * 64 + tid];
        bsum[tid] = s;
    }
    __syncthreads();
    int a = tid & 63, rg = tid >> 6;
    float ms = 0.f;
    for (int i = 0; i < 32; i++) {
        int r = rg * 32 + i;
        int n = row0 + r;
        float acc = bsum[a];
        if (n >= 15) {
#pragma unroll
            for (int j = 0; j < 16; j++) acc += ws[j * 64 + a] * ts[(r + j) * 64 + a];
        } else {
            for (int j = 0; j < 16; j++) {
                int lj = min(j, n) + 15;
                acc += ws[j * 64 + a] * ts[lj * 64 + a];
            }
        }
        g_rep[(size_t)n * 64 + a] = acc;
        if (orep) orep[(size_t)n * 64 + a] = acc;
        ms += acc;
    }
    mred[rg][a] = ms;
    __syncthreads();
    if (tid < 64)
        g_part[(size_t)blockIdx.x * MOMW + tid] =
            mred[0][tid] + mred[1][tid] + mred[2][tid] + mred[3][tid];
    int bi = tid & 15, ai = tid >> 4;
    int a4 = ai * 4, b4 = bi * 4;
    float sa[4][4] = {};
    const float* rp = &g_rep[(size_t)row0 * 64];
    for (int r = 0; r < 128; r++) {
        float4 av = *(const float4*)&rp[r * 64 + a4];
        float4 bv = *(const float4*)&rp[r * 64 + b4];
        float am[4] = {av.x, av.y, av.z, av.w};
        float bm[4] = {bv.x, bv.y, bv.z, bv.w};
#pragma unroll
        for (int i = 0; i < 4; i++)
#pragma unroll
            for (int j = 0; j < 4; j++) sa[i][j] = fmaf(am[i], bm[j], sa[i][j]);
    }
    float* sp = &g_part[(size_t)blockIdx.x * MOMW + 64];
#pragma unroll
    for (int i = 0; i < 4; i++)
        *(float4*)&sp[(a4 + i) * 64 + b4] = make_float4(sa[i][0], sa[i][1], sa[i][2], sa[i][3]);
}

// ---------------- K2b: reduce partials (deterministic, 4-way MLP) ----------------
__global__ void k2b_reduce() {
    int e = blockIdx.x * 128 + threadIdx.x;
    if (e >= MOMW) return;
    float s0 = 0.f, s1 = 0.f, s2 = 0.f, s3 = 0.f;
    for (int k = 0; k < NB2; k += 4) {
        s0 += g_part[(size_t)(k    ) * MOMW + e];
        s1 += g_part[(size_t)(k + 1) * MOMW + e];
        s2 += g_part[(size_t)(k + 2) * MOMW + e];
        s3 += g_part[(size_t)(k + 3) * MOMW + e];
    }
    float s = (s0 + s1) + (s2 + s3);
    if (e < 64) g_m[e] = s; else g_S[e - 64] = s;
}

// ---------------- K3: BN scale/shift via q = w^T S w (merged) ----------------
__global__ __launch_bounds__(256) void k3m(const float* __restrict__ W1,
                                           const float* __restrict__ gamma,
                                           const float* __restrict__ beta) {
    __shared__ float Ss[4096];
    __shared__ float Ws1[64 * 65];
    __shared__ float ms[64];
    __shared__ float qred[4][64], mured[4][64];
    int d = blockIdx.x, tid = threadIdx.x;
    for (int l = tid; l < 4096; l += 256) {
        Ss[l] = g_S[l];
        Ws1[(l >> 6) * 65 + (l & 63)] = W1[(size_t)d * 4096 + l];
    }
    if (tid < 64) ms[tid] = g_m[tid];
    __syncthreads();
    int b = tid & 63, iq = tid >> 6;
    float q = 0.f, mu = 0.f;
    for (int i = iq * 16; i < iq * 16 + 16; i++) {
        float wi = Ws1[i * 65 + b];
        mu = fmaf(ms[i], wi, mu);
        float tmp = 0.f;
#pragma unroll 8
        for (int j = 0; j < 64; j++) tmp = fmaf(Ss[i * 64 + j], Ws1[j * 65 + b], tmp);
        q = fmaf(wi, tmp, q);
    }
    qred[iq][b] = q; mured[iq][b] = mu;
    __syncthreads();
    if (tid < 64) {
        float Q  = qred[0][tid] + qred[1][tid] + qred[2][tid] + qred[3][tid];
        float MU = mured[0][tid] + mured[1][tid] + mured[2][tid] + mured[3][tid];
        const float invN = 1.0f / (float)NN;
        float mean = MU * invN;
        float var = Q * invN - mean * mean;
        float s = gamma[d * 64 + tid] * rsqrtf(var + 1e-5f);
        g_scale[d * 64 + tid] = s;
        g_shift[d * 64 + tid] = beta[d * 64 + tid] - mean * s;
    }
}

// ---------------- K4f: fused towers: (rep@W1 -> BN -> ELU) @ W2 + b2 ----------------
// 128-row tile, 512 thr, d-loop inside. H staged in smem; no global E tensor.
#define K4F_SMEM (32768 + 32768 + 16384 + 24576)  // Rs + Hs + Bs + Ws = 106496 B
__global__ __launch_bounds__(512, 2) void k4f(const float* __restrict__ W1,
                                              const float* __restrict__ W2,
                                              const float* __restrict__ b2,
                                              float* __restrict__ out) {
    extern __shared__ __align__(16) float sm[];
    float* Rs = sm;            // [128][64] rep tile
    float* Hs = sm + 8192;     // [128][64] post-ELU H
    float* Bs = sm + 16384;    // [64][64]  W1[d]
    float* Ws = sm + 20480;    // [64][96]  W2[d]
    int row0 = blockIdx.x * 128;
    int tid = threadIdx.x;

    for (int l = tid; l < 2048; l += 512) {
        int kk4 = (l & 15) * 4, r = l >> 4;
        *(float4*)&Rs[r * 64 + kk4] =
            *(const float4*)&g_rep[(size_t)(row0 + r) * 64 + kk4];
    }
    for (int l = tid; l < 1024; l += 512) {
        int c4 = (l & 15) * 4, kk = l >> 4;
        *(float4*)&Bs[kk * 64 + c4] = *(const float4*)&W1[kk * 64 + c4];
    }
    __syncthreads();

    int tc = tid & 15, tr = tid >> 4;     // GEMM1: 32 rowgroups x 16 colgroups
    int r1 = tr * 4, c1 = tc * 4;
    int c2 = tc * 6;                      // GEMM2: same split, 6 cols each
    for (int d = 0; d < 8; d++) {
        // ---- GEMM1: H = rep @ W1[d] ----
        float a1[4][4] = {};
#pragma unroll 8
        for (int kk = 0; kk < 64; ++kk) {
            float4 bv = *(const float4*)&Bs[kk * 64 + c1];
            float av[4];
#pragma unroll
            for (int i = 0; i < 4; i++) av[i] = Rs[(r1 + i) * 64 + kk];
#pragma unroll
            for (int i = 0; i < 4; i++) {
                a1[i][0] = fmaf(av[i], bv.x, a1[i][0]);
                a1[i][1] = fmaf(av[i], bv.y, a1[i][1]);
                a1[i][2] = fmaf(av[i], bv.z, a1[i][2]);
                a1[i][3] = fmaf(av[i], bv.w, a1[i][3]);
            }
        }
        __syncthreads();  // prev GEMM2 done with Hs/Ws; GEMM1 done with Bs
        // ---- BN + ELU -> Hs ----
        float sc[4], sf[4];
#pragma unroll
        for (int j = 0; j < 4; j++) {
            sc[j] = g_scale[d * 64 + c1 + j];
            sf[j] = g_shift[d * 64 + c1 + j];
        }
#pragma unroll
        for (int i = 0; i < 4; i++) {
            float4 v;
            v.x = eluf(fmaf(a1[i][0], sc[0], sf[0]));
            v.y = eluf(fmaf(a1[i][1], sc[1], sf[1]));
            v.z = eluf(fmaf(a1[i][2], sc[2], sf[2]));
            v.w = eluf(fmaf(a1[i][3], sc[3], sf[3]));
            *(float4*)&Hs[(r1 + i) * 64 + c1] = v;
        }
        // ---- stage W2[d] and next W1 ----
        for (int l = tid; l < 3072; l += 512) {
            int p2 = (l % 48) * 2, kk = l / 48;
            *(float2*)&Ws[kk * 96 + p2] =
                *(const float2*)&W2[(size_t)d * 6144 + kk * 96 + p2];
        }
        if (d < 7)
            for (int l = tid; l < 1024; l += 512) {
                int c4 = (l & 15) * 4, kk = l >> 4;
                *(float4*)&Bs[kk * 64 + c4] =
                    *(const float4*)&W1[(size_t)(d + 1) * 4096 + kk * 64 + c4];
            }
        __syncthreads();
        // ---- GEMM2: Y = H @ W2[d] + b2[d] ----
        float a2[4][6] = {};
#pragma unroll 8
        for (int kk = 0; kk < 64; ++kk) {
            float2 b0 = *(const float2*)&Ws[kk * 96 + c2];
            float2 b1 = *(const float2*)&Ws[kk * 96 + c2 + 2];
            float2 bq = *(const float2*)&Ws[kk * 96 + c2 + 4];
            float av[4];
#pragma unroll
            for (int i = 0; i < 4; i++) av[i] = Hs[(r1 + i) * 64 + kk];
#pragma unroll
            for (int i = 0; i < 4; i++) {
                a2[i][0] = fmaf(av[i], b0.x, a2[i][0]);
                a2[i][1] = fmaf(av[i], b0.y, a2[i][1]);
                a2[i][2] = fmaf(av[i], b1.x, a2[i][2]);
                a2[i][3] = fmaf(av[i], b1.y, a2[i][3]);
                a2[i][4] = fmaf(av[i], bq.x, a2[i][4]);
                a2[i][5] = fmaf(av[i], bq.y, a2[i][5]);
            }
        }
        float bb[6];
#pragma unroll
        for (int j = 0; j < 6; j++) bb[j] = b2[d * 96 + c2 + j];
#pragma unroll
        for (int i = 0; i < 4; i++) {
            size_t rowb = (size_t)(row0 + r1 + i) * 768;
#pragma unroll
            for (int j = 0; j < 6; j++)
                out[rowb + (size_t)(c2 + j) * 8 + d] = a2[i][j] + bb[j];
        }
    }
}

// ---------------- launch ----------------
extern "C" void kernel_launch(void* const* d_in, const int* in_sizes, int n_in,
                              void* d_out, int out_size) {
    const float* x     = (const float*)d_in[0];
    const float* shz   = (const float*)d_in[1];
    const float* lw    = (const float*)d_in[2];
    const float* lb    = (const float*)d_in[3];
    const float* W1    = (const float*)d_in[4];
    // d_in[5] = b1: cancels exactly inside BatchNorm (h - mu), unused
    const float* gamma = (const float*)d_in[6];
    const float* beta  = (const float*)d_in[7];
    const float* W2    = (const float*)d_in[8];
    const float* b2    = (const float*)d_in[9];
    float* out = (float*)d_out;

    float* orep = nullptr;
    if ((long long)out_size >= (long long)NN * 832)
        orep = out + (size_t)NN * 768;

    cudaFuncSetAttribute(k4f, cudaFuncAttributeMaxDynamicSharedMemorySize, K4F_SMEM);

    k1_gemm_norm<<<NN / 128, 256>>>(x, shz);
    k2_rep<<<NN / 128, 256>>>(lw, lb, orep);
    k2b_reduce<<<(MOMW + 127) / 128, 128>>>();
    k3m<<<DD, 256>>>(W1, gamma, beta);
    k4f<<<NN / 128, 512, K4F_SMEM>>>(W1, W2, b2, out);
}